// round 17
// baseline (speedup 1.0000x reference)
#include <cuda_runtime.h>
#include <cuda_bf16.h>
#include <cstdint>

#define N_USER 100000
#define N_GAME 50000
#define DDIM   256
#define EMAX   200000

// ---------------- scratch (device globals) ----------------
__device__ int   g_rp_u[N_USER + 1];
__device__ int   g_rp_g[N_GAME + 1];
__device__ int   g_cur_u[N_USER];
__device__ int   g_cur_g[N_GAME];
__device__ int   g_srcs_u[EMAX];
__device__ int   g_srcs_g[EMAX];
__device__ int   g_part_u[128];
__device__ int   g_part_g[128];
__device__ float g_tmpA[DDIM * DDIM];   // Wm_played @ Wout_game
__device__ float g_tmpB[DDIM * DDIM];   // Wm_rev @ Wout_user
__device__ __nv_bfloat16 g_Wub[DDIM * DDIM];  // bf16(0.125 * Wv_game @ tmpB)
__device__ __nv_bfloat16 g_Wgb[DDIM * DDIM];  // bf16(0.125 * Wv_user @ tmpA)
__device__ float g_eu[DDIM];
__device__ float g_eg[DDIM];
__device__ __nv_bfloat16 g_Yg[(size_t)N_USER * DDIM];  // x_user @ Wgb
__device__ __nv_bfloat16 g_Yu[(size_t)N_GAME * DDIM];  // x_game @ Wub

// ---------------- side stream + events (created pre-main) ------
static cudaStream_t g_s2 = 0;
static cudaEvent_t  g_e1 = 0, g_e3 = 0, g_e5 = 0;
namespace {
struct StreamInit {
    StreamInit() {
        if (cudaStreamCreateWithFlags(&g_s2, cudaStreamNonBlocking) != cudaSuccess)
            g_s2 = 0;
        bool ok = true;
        ok &= (cudaEventCreateWithFlags(&g_e1, cudaEventDisableTiming) == cudaSuccess);
        ok &= (cudaEventCreateWithFlags(&g_e3, cudaEventDisableTiming) == cudaSuccess);
        ok &= (cudaEventCreateWithFlags(&g_e5, cudaEventDisableTiming) == cudaSuccess);
        if (!ok) g_s2 = 0;   // fall back to fully serial legacy stream
    }
};
StreamInit g_stream_init;
}

// ---------------- kernel 0: 64x64-tile weight GEMM pair + edge histogram ----
__global__ void k0_gemm_hist(const float* __restrict__ A0, const float* __restrict__ B0,
                             float* __restrict__ C0,
                             const float* __restrict__ A1, const float* __restrict__ B1,
                             float* __restrict__ C1,
                             const int* __restrict__ pd, const int* __restrict__ rd, int E,
                             int* __restrict__ rp_g, int* __restrict__ rp_u)
{
    if (blockIdx.z >= 2) {
        int base = ((blockIdx.z - 2) * 16 + blockIdx.y * 4 + blockIdx.x) * 256 + threadIdx.x;
        for (int i = base; i < E; i += 32 * 256) {
            atomicAdd(&rp_g[pd[i] + 1], 1);
            atomicAdd(&rp_u[rd[i] + 1], 1);
        }
        return;
    }
    const float* A = blockIdx.z ? A1 : A0;
    const float* B = blockIdx.z ? B1 : B0;
    float*       C = blockIdx.z ? C1 : C0;
    __shared__ float As[16][64];
    __shared__ float Bs[16][64];
    const int tid = threadIdx.x;
    const int tx = tid & 15, ty = tid >> 4;
    const int row0 = blockIdx.y * 64, col0 = blockIdx.x * 64;
    const int arow = tid >> 2, ac4 = (tid & 3) * 4;
    const int brow = tid >> 4, bc4 = (tid & 15) * 4;
    float acc[4][4];
#pragma unroll
    for (int i = 0; i < 4; i++)
#pragma unroll
        for (int j = 0; j < 4; j++) acc[i][j] = 0.f;

    for (int kk = 0; kk < 256; kk += 16) {
        float4 av = *(const float4*)(A + (size_t)(row0 + arow) * 256 + kk + ac4);
        As[ac4 + 0][arow] = av.x;
        As[ac4 + 1][arow] = av.y;
        As[ac4 + 2][arow] = av.z;
        As[ac4 + 3][arow] = av.w;
        float4 bv = *(const float4*)(B + (size_t)(kk + brow) * 256 + col0 + bc4);
        *(float4*)&Bs[brow][bc4] = bv;
        __syncthreads();
#pragma unroll
        for (int k = 0; k < 16; k++) {
            float4 a = *(const float4*)&As[k][ty * 4];
            float4 b = *(const float4*)&Bs[k][tx * 4];
            float ar[4] = {a.x, a.y, a.z, a.w};
            float br[4] = {b.x, b.y, b.z, b.w};
#pragma unroll
            for (int i = 0; i < 4; i++)
#pragma unroll
                for (int j = 0; j < 4; j++) acc[i][j] += ar[i] * br[j];
        }
        __syncthreads();
    }
#pragma unroll
    for (int i = 0; i < 4; i++) {
        float4 o = make_float4(acc[i][0], acc[i][1], acc[i][2], acc[i][3]);
        *(float4*)(C + (size_t)(row0 + ty * 4 + i) * 256 + col0 + tx * 4) = o;
    }
}

// ---------------- kernel 1: bf16 weight GEMM pair + fused bias combo ----------
__global__ void k1_gemmbf_combo(const float* __restrict__ A0, const float* __restrict__ B0,
                                __nv_bfloat16* __restrict__ C0,
                                const float* __restrict__ A1, const float* __restrict__ B1,
                                __nv_bfloat16* __restrict__ C1, float scale,
                                const float* __restrict__ bv0, const float* __restrict__ T0,
                                const float* __restrict__ bm0, const float* __restrict__ W0,
                                float* __restrict__ e0,
                                const float* __restrict__ bv1, const float* __restrict__ T1,
                                const float* __restrict__ bm1, const float* __restrict__ W1,
                                float* __restrict__ e1)
{
    if (blockIdx.z == 2) {
        if (blockIdx.y != 0 || blockIdx.x >= 2) return;
        const float* bv = blockIdx.x ? bv1 : bv0;
        const float* T  = blockIdx.x ? T1  : T0;
        const float* bm = blockIdx.x ? bm1 : bm0;
        const float* W  = blockIdx.x ? W1  : W0;
        float*       e  = blockIdx.x ? e1  : e0;
        int n = threadIdx.x;
        float acc = 0.f;
#pragma unroll 8
        for (int j = 0; j < 256; j++)
            acc += bv[j] * T[j * 256 + n] + bm[j] * W[j * 256 + n];
        e[n] = 0.125f * acc;
        return;
    }
    const float* A = blockIdx.z ? A1 : A0;
    const float* B = blockIdx.z ? B1 : B0;
    __nv_bfloat16* C = blockIdx.z ? C1 : C0;
    __shared__ float As[16][64];
    __shared__ float Bs[16][64];
    const int tid = threadIdx.x;
    const int tx = tid & 15, ty = tid >> 4;
    const int row0 = blockIdx.y * 64, col0 = blockIdx.x * 64;
    const int arow = tid >> 2, ac4 = (tid & 3) * 4;
    const int brow = tid >> 4, bc4 = (tid & 15) * 4;
    float acc[4][4];
#pragma unroll
    for (int i = 0; i < 4; i++)
#pragma unroll
        for (int j = 0; j < 4; j++) acc[i][j] = 0.f;

    for (int kk = 0; kk < 256; kk += 16) {
        float4 av = *(const float4*)(A + (size_t)(row0 + arow) * 256 + kk + ac4);
        As[ac4 + 0][arow] = av.x;
        As[ac4 + 1][arow] = av.y;
        As[ac4 + 2][arow] = av.z;
        As[ac4 + 3][arow] = av.w;
        float4 bv = *(const float4*)(B + (size_t)(kk + brow) * 256 + col0 + bc4);
        *(float4*)&Bs[brow][bc4] = bv;
        __syncthreads();
#pragma unroll
        for (int k = 0; k < 16; k++) {
            float4 a = *(const float4*)&As[k][ty * 4];
            float4 b = *(const float4*)&Bs[k][tx * 4];
            float ar[4] = {a.x, a.y, a.z, a.w};
            float br[4] = {b.x, b.y, b.z, b.w};
#pragma unroll
            for (int i = 0; i < 4; i++)
#pragma unroll
                for (int j = 0; j < 4; j++) acc[i][j] += ar[i] * br[j];
        }
        __syncthreads();
    }
#pragma unroll
    for (int i = 0; i < 4; i++) {
#pragma unroll
        for (int j = 0; j < 4; j++)
            C[(size_t)(row0 + ty * 4 + i) * 256 + col0 + tx * 4 + j] =
                __float2bfloat16(acc[i][j] * scale);
    }
}

// ---------------- scan kernels ----------------
__global__ void scanA(const int* __restrict__ in_u, int len_u, int* __restrict__ part_u,
                      const int* __restrict__ in_g, int len_g, int* __restrict__ part_g)
{
    const int* in  = blockIdx.y ? in_g  : in_u;
    const int len  = blockIdx.y ? len_g : len_u;
    int* part      = blockIdx.y ? part_g : part_u;
    int t = threadIdx.x;
    int idx = blockIdx.x * 1024 + t;
    int v = (idx < len) ? in[idx] : 0;
    int lane = t & 31, wid = t >> 5;
#pragma unroll
    for (int o = 16; o; o >>= 1) v += __shfl_down_sync(0xFFFFFFFFu, v, o);
    __shared__ int ws[32];
    if (lane == 0) ws[wid] = v;
    __syncthreads();
    if (wid == 0) {
        int s = ws[lane];
#pragma unroll
        for (int o = 16; o; o >>= 1) s += __shfl_down_sync(0xFFFFFFFFu, s, o);
        if (lane == 0) part[blockIdx.x] = s;
    }
}

__global__ void scanC(int* __restrict__ rp_u, int len_u, const int* __restrict__ part_u,
                      int* __restrict__ cur_u,
                      int* __restrict__ rp_g, int len_g, const int* __restrict__ part_g,
                      int* __restrict__ cur_g)
{
    int* rp         = blockIdx.y ? rp_g  : rp_u;
    const int len   = blockIdx.y ? len_g : len_u;
    const int* part = blockIdx.y ? part_g : part_u;
    int* cur        = blockIdx.y ? cur_g : cur_u;

    __shared__ int sp[128];
    int t = threadIdx.x;
    if (t < 128) sp[t] = (t < (int)gridDim.x) ? part[t] : 0;
    __syncthreads();
    int offset = 0;
    for (int j = 0; j < (int)blockIdx.x; j++) offset += sp[j];

    int idx = blockIdx.x * 1024 + t;
    int x = (idx < len) ? rp[idx] : 0;
    int lane = t & 31, wid = t >> 5;
#pragma unroll
    for (int o = 1; o < 32; o <<= 1) {
        int n = __shfl_up_sync(0xFFFFFFFFu, x, o);
        if (lane >= o) x += n;
    }
    __shared__ int wsum[32];
    if (lane == 31) wsum[wid] = x;
    __syncthreads();
    if (wid == 0) {
        int y = wsum[lane];
#pragma unroll
        for (int o = 1; o < 32; o <<= 1) {
            int n = __shfl_up_sync(0xFFFFFFFFu, y, o);
            if (lane >= o) y += n;
        }
        wsum[lane] = y;
    }
    __syncthreads();
    int incl = x + (wid > 0 ? wsum[wid - 1] : 0) + offset;
    if (idx < len) {
        rp[idx] = incl;
        if (idx < len - 1) cur[idx] = incl;
    }
}

__global__ void bin_kernel(const int* __restrict__ ps, const int* __restrict__ pd,
                           const int* __restrict__ rs, const int* __restrict__ rd, int E,
                           int* __restrict__ cur_g, int* __restrict__ srcs_g,
                           int* __restrict__ cur_u, int* __restrict__ srcs_u)
{
    int i = blockIdx.x * blockDim.x + threadIdx.x;
    if (i < E) {
        int dg = pd[i];
        int p = atomicAdd(&cur_g[dg], 1);
        srcs_g[p] = ps[i];
        int du = rd[i];
        int q = atomicAdd(&cur_u[du], 1);
        srcs_u[q] = rs[i];
    }
}

// ---------------- MMA helpers ----------------
__device__ __forceinline__ uint32_t smem_u32(const void* p)
{
    return (uint32_t)__cvta_generic_to_shared(p);
}

__device__ __forceinline__ void ldsm_x4(uint32_t* r, uint32_t addr)
{
    asm volatile("ldmatrix.sync.aligned.m8n8.x4.shared.b16 {%0,%1,%2,%3}, [%4];"
                 : "=r"(r[0]), "=r"(r[1]), "=r"(r[2]), "=r"(r[3]) : "r"(addr));
}

__device__ __forceinline__ void ldsm_x4_t(uint32_t* r, uint32_t addr)
{
    asm volatile("ldmatrix.sync.aligned.m8n8.x4.trans.shared.b16 {%0,%1,%2,%3}, [%4];"
                 : "=r"(r[0]), "=r"(r[1]), "=r"(r[2]), "=r"(r[3]) : "r"(addr));
}

__device__ __forceinline__ void mma_bf16(float* c, const uint32_t* a, const uint32_t* b)
{
    asm volatile("mma.sync.aligned.m16n8k16.row.col.f32.bf16.bf16.f32 "
                 "{%0,%1,%2,%3}, {%4,%5,%6,%7}, {%8,%9}, {%0,%1,%2,%3};"
                 : "+f"(c[0]), "+f"(c[1]), "+f"(c[2]), "+f"(c[3])
                 : "r"(a[0]), "r"(a[1]), "r"(a[2]), "r"(a[3]), "r"(b[0]), "r"(b[1]));
}

// ---------------- gemmY: persistent, B fully smem-resident, parameterized ----
// 148 blocks, 256 threads, warp grid 2M x 4N, warp tile 32x64, 64-row tiles.
#define GY_BLOCKS 148
#define SMP_A_OFF   (256 * 264 * 2)                 // 135168
#define SMP_TOTAL   (SMP_A_OFF + 2 * 64 * 264 * 2)  // 202752

__global__ __launch_bounds__(256, 1)
void gemmY(const float* __restrict__ X, const __nv_bfloat16* __restrict__ Wb,
           __nv_bfloat16* __restrict__ Y, int ntile, int M)
{
    extern __shared__ char smem[];
    __nv_bfloat16* Bsm = (__nv_bfloat16*)smem;
    __nv_bfloat16* Abf = (__nv_bfloat16*)(smem + SMP_A_OFF);

    const int tid = threadIdx.x;
    const int lane = tid & 31;
    const int warp = tid >> 5;
    const int b = blockIdx.x;
    const int stride = gridDim.x;

    // ---- load full B into smem once (256 rows x 256 bf16) ----
    {
        const int brow = tid >> 5;
        const int bq = tid & 31;
#pragma unroll
        for (int c = 0; c < 16; c++) {
            int r0 = c * 16 + brow;
            int r1 = r0 + 8;
            uint4 v0 = *(const uint4*)(Wb + (size_t)r0 * 256 + bq * 8);
            uint4 v1 = *(const uint4*)(Wb + (size_t)r1 * 256 + bq * 8);
            *(uint4*)(Bsm + r0 * 264 + bq * 8) = v0;
            *(uint4*)(Bsm + r1 * 264 + bq * 8) = v1;
        }
    }

    const float4* X4 = (const float4*)X;
    auto loadA = [&](int bm0, int buf) {
#pragma unroll
        for (int i = 0; i < 8; i++) {
            const int rl = warp * 8 + i;
            const int r = bm0 + rl;
            float4 a0 = make_float4(0.f, 0.f, 0.f, 0.f);
            float4 a1 = make_float4(0.f, 0.f, 0.f, 0.f);
            if (r < M) {
                a0 = X4[(size_t)r * 64 + lane];
                a1 = X4[(size_t)r * 64 + 32 + lane];
            }
            __nv_bfloat162 h00 = __floats2bfloat162_rn(a0.x, a0.y);
            __nv_bfloat162 h01 = __floats2bfloat162_rn(a0.z, a0.w);
            __nv_bfloat162 h10 = __floats2bfloat162_rn(a1.x, a1.y);
            __nv_bfloat162 h11 = __floats2bfloat162_rn(a1.z, a1.w);
            uint2 w0; w0.x = *(uint32_t*)&h00; w0.y = *(uint32_t*)&h01;
            uint2 w1; w1.x = *(uint32_t*)&h10; w1.y = *(uint32_t*)&h11;
            __nv_bfloat16* dst = Abf + buf * (64 * 264) + rl * 264;
            *(uint2*)(dst + lane * 4) = w0;
            *(uint2*)(dst + 128 + lane * 4) = w1;
        }
    };

    if (b < ntile) loadA(b * 64, 0);
    __syncthreads();

    const int wm0 = (warp >> 2) * 32;
    const int wn0 = (warp & 3) * 64;
    const uint32_t bBase = smem_u32(Bsm);
    const uint32_t aBase = smem_u32(Abf);
    const int groupID = lane >> 2;
    const int tig = lane & 3;

    int bufi = 0;
    for (int t = b; t < ntile; t += stride, bufi ^= 1) {
        const int bm0 = t * 64;

        float acc[2][8][4];
#pragma unroll
        for (int mt = 0; mt < 2; mt++)
#pragma unroll
            for (int nt = 0; nt < 8; nt++)
#pragma unroll
                for (int j = 0; j < 4; j++) acc[mt][nt][j] = 0.f;

        const uint32_t aB = aBase + (uint32_t)bufi * (64 * 264 * 2);
#pragma unroll 4
        for (int it = 0; it < 16; it++) {
            uint32_t ra[2][4];
#pragma unroll
            for (int mt = 0; mt < 2; mt++) {
                uint32_t addr = aB + (uint32_t)(wm0 + mt * 16 + (lane & 15)) * 528u
                              + (uint32_t)(lane >> 4) * 16u + (uint32_t)it * 32u;
                ldsm_x4(ra[mt], addr);
            }
#pragma unroll
            for (int p = 0; p < 4; p++) {
                uint32_t rb[4];
                uint32_t addr = bBase + (uint32_t)(it * 16 + (lane & 15)) * 528u
                              + (uint32_t)(wn0 + p * 16 + ((lane >> 4) * 8)) * 2u;
                ldsm_x4_t(rb, addr);
#pragma unroll
                for (int mt = 0; mt < 2; mt++) {
                    mma_bf16(acc[mt][2 * p + 0], ra[mt], rb + 0);
                    mma_bf16(acc[mt][2 * p + 1], ra[mt], rb + 2);
                }
            }
        }

        const int tn = t + stride;
        if (tn < ntile) loadA(tn * 64, bufi ^ 1);

#pragma unroll
        for (int nt = 0; nt < 8; nt++) {
            const int col = wn0 + nt * 8 + tig * 2;
#pragma unroll
            for (int mt = 0; mt < 2; mt++) {
                const int row0 = bm0 + wm0 + mt * 16 + groupID;
                if (row0 < M) {
                    __nv_bfloat162 h = __floats2bfloat162_rn(acc[mt][nt][0], acc[mt][nt][1]);
                    *(__nv_bfloat162*)(Y + (size_t)row0 * 256 + col) = h;
                }
                const int row1 = row0 + 8;
                if (row1 < M) {
                    __nv_bfloat162 h = __floats2bfloat162_rn(acc[mt][nt][2], acc[mt][nt][3]);
                    *(__nv_bfloat162*)(Y + (size_t)row1 * 256 + col) = h;
                }
            }
        }
        __syncthreads();
    }
}

// ---------------- gather_ep: warp-per-row bf16 Y gather + epilogue (one pass) --
#define GR_ROWS 64

__global__ __launch_bounds__(256)
void gather_ep(const int* __restrict__ rowptr, const int* __restrict__ srcs,
               const __nv_bfloat16* __restrict__ Ysrc,
               const float* __restrict__ Xres,
               const float* __restrict__ extra, const float* __restrict__ bout,
               float* __restrict__ Outb, int M)
{
    const int lane = threadIdx.x & 31;
    const int warp = threadIdx.x >> 5;
    const int r0 = blockIdx.x * GR_ROWS;
    const uint4* Y4 = (const uint4*)Ysrc;

    const float4 bo0 = *(const float4*)(bout + lane * 8);
    const float4 bo1 = *(const float4*)(bout + lane * 8 + 4);
    const float4 ev0 = *(const float4*)(extra + lane * 8);
    const float4 ev1 = *(const float4*)(extra + lane * 8 + 4);

    const int rend = (r0 + GR_ROWS < M) ? r0 + GR_ROWS : M;
#pragma unroll 1
    for (int r = r0 + warp; r < rend; r += 8) {
        const int beg = __ldg(rowptr + r);
        const int end = __ldg(rowptr + r + 1);
        float acc[8];
#pragma unroll
        for (int j = 0; j < 8; j++) acc[j] = 0.f;

        int e = beg;
        for (; e + 1 < end; e += 2) {
            int s0 = __ldg(srcs + e), s1 = __ldg(srcs + e + 1);
            uint4 v0 = Y4[(size_t)s0 * 32 + lane];
            uint4 v1 = Y4[(size_t)s1 * 32 + lane];
            float2 f;
            f = __bfloat1622float2(*(__nv_bfloat162*)&v0.x); acc[0] += f.x; acc[1] += f.y;
            f = __bfloat1622float2(*(__nv_bfloat162*)&v0.y); acc[2] += f.x; acc[3] += f.y;
            f = __bfloat1622float2(*(__nv_bfloat162*)&v0.z); acc[4] += f.x; acc[5] += f.y;
            f = __bfloat1622float2(*(__nv_bfloat162*)&v0.w); acc[6] += f.x; acc[7] += f.y;
            f = __bfloat1622float2(*(__nv_bfloat162*)&v1.x); acc[0] += f.x; acc[1] += f.y;
            f = __bfloat1622float2(*(__nv_bfloat162*)&v1.y); acc[2] += f.x; acc[3] += f.y;
            f = __bfloat1622float2(*(__nv_bfloat162*)&v1.z); acc[4] += f.x; acc[5] += f.y;
            f = __bfloat1622float2(*(__nv_bfloat162*)&v1.w); acc[6] += f.x; acc[7] += f.y;
        }
        if (e < end) {
            int s0 = __ldg(srcs + e);
            uint4 v0 = Y4[(size_t)s0 * 32 + lane];
            float2 f;
            f = __bfloat1622float2(*(__nv_bfloat162*)&v0.x); acc[0] += f.x; acc[1] += f.y;
            f = __bfloat1622float2(*(__nv_bfloat162*)&v0.y); acc[2] += f.x; acc[3] += f.y;
            f = __bfloat1622float2(*(__nv_bfloat162*)&v0.z); acc[4] += f.x; acc[5] += f.y;
            f = __bfloat1622float2(*(__nv_bfloat162*)&v0.w); acc[6] += f.x; acc[7] += f.y;
        }

        const int deg = end - beg;
        const float inv = 1.0f / (float)(deg > 1 ? deg : 1);
        const float on = (deg > 0) ? 1.0f : 0.0f;
        const float4 x0 = *(const float4*)(Xres + (size_t)r * 256 + lane * 8);
        const float4 x1 = *(const float4*)(Xres + (size_t)r * 256 + lane * 8 + 4);
        float4 o0, o1;
        o0.x = fmaxf(acc[0] * inv + bo0.x + on * ev0.x + x0.x, 0.f);
        o0.y = fmaxf(acc[1] * inv + bo0.y + on * ev0.y + x0.y, 0.f);
        o0.z = fmaxf(acc[2] * inv + bo0.z + on * ev0.z + x0.z, 0.f);
        o0.w = fmaxf(acc[3] * inv + bo0.w + on * ev0.w + x0.w, 0.f);
        o1.x = fmaxf(acc[4] * inv + bo1.x + on * ev1.x + x1.x, 0.f);
        o1.y = fmaxf(acc[5] * inv + bo1.y + on * ev1.y + x1.y, 0.f);
        o1.z = fmaxf(acc[6] * inv + bo1.z + on * ev1.z + x1.z, 0.f);
        o1.w = fmaxf(acc[7] * inv + bo1.w + on * ev1.w + x1.w, 0.f);
        *(float4*)(Outb + (size_t)r * 256 + lane * 8) = o0;
        *(float4*)(Outb + (size_t)r * 256 + lane * 8 + 4) = o1;
    }
}

// ---------------- host launch ----------------
extern "C" void kernel_launch(void* const* d_in, const int* in_sizes, int n_in,
                              void* d_out, int out_size)
{
    const float* x_user    = (const float*)d_in[0];
    const float* x_game    = (const float*)d_in[1];
    const float* Wv_user   = (const float*)d_in[6];
    const float* bv_user   = (const float*)d_in[7];
    const float* Wout_user = (const float*)d_in[8];
    const float* bout_user = (const float*)d_in[9];
    const float* Wv_game   = (const float*)d_in[14];
    const float* bv_game   = (const float*)d_in[15];
    const float* Wout_game = (const float*)d_in[16];
    const float* bout_game = (const float*)d_in[17];
    const float* Wm_played = (const float*)d_in[20];
    const float* bm_played = (const float*)d_in[21];
    const float* Wm_rev    = (const float*)d_in[24];
    const float* bm_rev    = (const float*)d_in[25];
    const int* ps = (const int*)d_in[26];
    const int* pd = (const int*)d_in[27];
    const int* rs = (const int*)d_in[28];
    const int* rd = (const int*)d_in[29];
    const int E = in_sizes[26];

    float* out = (float*)d_out;

    float *tmpA, *tmpB, *eu, *eg;
    int *rp_u, *rp_g, *cur_u, *cur_g, *srcs_u, *srcs_g, *part_u, *part_g;
    __nv_bfloat16 *Wub, *Wgb, *Yg, *Yu;
    cudaGetSymbolAddress((void**)&rp_u,   g_rp_u);
    cudaGetSymbolAddress((void**)&rp_g,   g_rp_g);
    cudaGetSymbolAddress((void**)&cur_u,  g_cur_u);
    cudaGetSymbolAddress((void**)&cur_g,  g_cur_g);
    cudaGetSymbolAddress((void**)&srcs_u, g_srcs_u);
    cudaGetSymbolAddress((void**)&srcs_g, g_srcs_g);
    cudaGetSymbolAddress((void**)&part_u, g_part_u);
    cudaGetSymbolAddress((void**)&part_g, g_part_g);
    cudaGetSymbolAddress((void**)&tmpA,   g_tmpA);
    cudaGetSymbolAddress((void**)&tmpB,   g_tmpB);
    cudaGetSymbolAddress((void**)&Wub,    g_Wub);
    cudaGetSymbolAddress((void**)&Wgb,    g_Wgb);
    cudaGetSymbolAddress((void**)&eu,     g_eu);
    cudaGetSymbolAddress((void**)&eg,     g_eg);
    cudaGetSymbolAddress((void**)&Yg,     g_Yg);
    cudaGetSymbolAddress((void**)&Yu,     g_Yu);

    cudaFuncSetAttribute(gemmY,
                         cudaFuncAttributeMaxDynamicSharedMemorySize, SMP_TOTAL);

    const int len_u = N_USER + 1, len_g = N_GAME + 1;
    const int sgx = (len_u + 1023) / 1024;
    const int NTU = (N_USER + 63) / 64;   // Yg tiles (user rows)  = 1563
    const int NTG = (N_GAME + 63) / 64;   // Yu tiles (game rows)  = 782
    const int GRU = (N_USER + GR_ROWS - 1) / GR_ROWS;   // 1563
    const int GRG = (N_GAME + GR_ROWS - 1) / GR_ROWS;   // 782
    const bool fork = (g_s2 != 0);
    cudaStream_t s2 = fork ? g_s2 : 0;

    // main: zero rowptrs
    cudaMemsetAsync(rp_u, 0, (size_t)(N_USER + 1) * sizeof(int));
    cudaMemsetAsync(rp_g, 0, (size_t)(N_GAME + 1) * sizeof(int));

    // main: weight-chain GEMM pair + histogram (fork point for CSR)
    k0_gemm_hist<<<dim3(4, 4, 4), 256>>>(Wm_played, Wout_game, tmpA,
                                         Wm_rev, Wout_user, tmpB,
                                         pd, rd, E, rp_g, rp_u);
    if (fork) {
        cudaEventRecord(g_e1, 0);
        cudaStreamWaitEvent(s2, g_e1, 0);
    }

    // main: bf16 weight GEMM pair + bias combo
    k1_gemmbf_combo<<<dim3(4, 4, 3), 256>>>(Wv_user, tmpA, Wgb,
                                            Wv_game, tmpB, Wub, 0.125f,
                                            bv_user, tmpA, bm_played, Wout_game, eg,
                                            bv_game, tmpB, bm_rev, Wout_user, eu);
    // side: CSR chain
    scanA<<<dim3(sgx, 2), 1024, 0, s2>>>(rp_u, len_u, part_u, rp_g, len_g, part_g);

    // main (profiled idx 5): Yu = bf16(x_game @ Wub)  -- the small third
    gemmY<<<GY_BLOCKS, 256, SMP_TOTAL>>>(x_game, Wub, Yu, NTG, N_GAME);
    if (fork) {
        cudaEventRecord(g_e3, 0);          // Yu ready
        cudaStreamWaitEvent(s2, g_e3, 0);
    }

    // side: finish CSR
    scanC<<<dim3(sgx, 2), 1024, 0, s2>>>(rp_u, len_u, part_u, cur_u,
                                         rp_g, len_g, part_g, cur_g);
    bin_kernel<<<(E + 255) / 256, 256, 0, s2>>>(ps, pd, rs, rd, E,
                                                cur_g, srcs_g, cur_u, srcs_u);
    // side: user-dst gather (needs Yu + CSR) -- overlaps gemmY(Yg) on main
    gather_ep<<<GRU, 256, 0, s2>>>(rp_u, srcs_u, Yu, x_user, eu, bout_user,
                                   out, N_USER);

    // main: Yg = bf16(x_user @ Wgb)  -- the big two-thirds, concurrent with gather_u
    gemmY<<<GY_BLOCKS, 256, SMP_TOTAL>>>(x_user, Wgb, Yg, NTU, N_USER);

    if (fork) {
        cudaEventRecord(g_e5, s2);         // gather_u (and CSR) done
        cudaStreamWaitEvent(0, g_e5, 0);   // join side stream into main
    }
    // main: game-dst gather (needs Yg + CSR)
    gather_ep<<<GRG, 256>>>(rp_g, srcs_g, Yg, x_game, eg, bout_game,
                            out + (size_t)N_USER * DDIM, N_GAME);
}